// round 10
// baseline (speedup 1.0000x reference)
#include <cuda_runtime.h>
#include <cuda_bf16.h>

// DotPredictor: out[e] = sigmoid(dot(h[src[e]], h[dst[e]])), D = 64 fp32.
// Indices are int32 (JAX x64 disabled).
// Persistent grid-stride kernel: 8 lanes per group, 2 edges per group,
// 8 LDG.128/thread per iteration (full 128B lines per warp-level LDG).
// Next iteration's indices are prefetched before the current reduction,
// hiding index-load latency. Sigmoid via tanh.approx (single MUFU).

#define D 64

__device__ __forceinline__ float fast_sigmoid(float x)
{
    // sigmoid(x) = 0.5 * tanh(x/2) + 0.5 ; tanh.approx err ~2^-11, well
    // within the 1e-3 budget.
    float t;
    asm("tanh.approx.f32 %0, %1;" : "=f"(t) : "f"(x * 0.5f));
    return fmaf(t, 0.5f, 0.5f);
}

template <bool EVEN_E>
__global__ void __launch_bounds__(256) dotpred_kernel(
    const float* __restrict__ h,
    const int* __restrict__ src,
    const int* __restrict__ dst,
    float* __restrict__ out,
    int E,
    int ngroups,
    int gstride)
{
    int tid   = blockIdx.x * blockDim.x + threadIdx.x;
    int lane  = tid & 7;
    int g     = tid >> 3;
    if (g >= ngroups) return;

    const int2* __restrict__ src2 = reinterpret_cast<const int2*>(src);
    const int2* __restrict__ dst2 = reinterpret_cast<const int2*>(dst);

    // Prime the pipeline: indices for the first iteration
    int2 ss = src2[g];
    int2 dd = dst2[g];

    while (true) {
        int  gn   = g + gstride;
        bool more = (gn < ngroups);

        int e0 = g * 2;
        int s1i, d1i;
        if (EVEN_E) {
            s1i = ss.y;
            d1i = dd.y;
        } else {
            bool has_e1 = (e0 + 1 < E);
            s1i = has_e1 ? ss.y : ss.x;
            d1i = has_e1 ? dd.y : dd.x;
        }

        const float4* __restrict__ s0p =
            reinterpret_cast<const float4*>(h + (long long)ss.x * D);
        const float4* __restrict__ d0p =
            reinterpret_cast<const float4*>(h + (long long)dd.x * D);
        const float4* __restrict__ s1p =
            reinterpret_cast<const float4*>(h + (long long)s1i * D);
        const float4* __restrict__ d1p =
            reinterpret_cast<const float4*>(h + (long long)d1i * D);

        // 8 independent 16B loads; each warp-level LDG covers 4 full 128B lines
        float4 a0 = s0p[lane];
        float4 a1 = s0p[lane + 8];
        float4 b0 = d0p[lane];
        float4 b1 = d0p[lane + 8];
        float4 c0 = s1p[lane];
        float4 c1 = s1p[lane + 8];
        float4 f0 = d1p[lane];
        float4 f1 = d1p[lane + 8];

        // Prefetch next iteration's indices while the row gathers are in flight
        int2 ssn, ddn;
        if (more) {
            ssn = src2[gn];
            ddn = dst2[gn];
        }

        float acc0 = a0.x * b0.x;
        float acc1 = c0.x * f0.x;
        acc0 = fmaf(a0.y, b0.y, acc0);
        acc1 = fmaf(c0.y, f0.y, acc1);
        acc0 = fmaf(a0.z, b0.z, acc0);
        acc1 = fmaf(c0.z, f0.z, acc1);
        acc0 = fmaf(a0.w, b0.w, acc0);
        acc1 = fmaf(c0.w, f0.w, acc1);
        acc0 = fmaf(a1.x, b1.x, acc0);
        acc1 = fmaf(c1.x, f1.x, acc1);
        acc0 = fmaf(a1.y, b1.y, acc0);
        acc1 = fmaf(c1.y, f1.y, acc1);
        acc0 = fmaf(a1.z, b1.z, acc0);
        acc1 = fmaf(c1.z, f1.z, acc1);
        acc0 = fmaf(a1.w, b1.w, acc0);
        acc1 = fmaf(c1.w, f1.w, acc1);

        // Plain 6-shuffle reduction (keeps register count low)
        acc0 += __shfl_xor_sync(0xFFFFFFFFu, acc0, 4);
        acc1 += __shfl_xor_sync(0xFFFFFFFFu, acc1, 4);
        acc0 += __shfl_xor_sync(0xFFFFFFFFu, acc0, 2);
        acc1 += __shfl_xor_sync(0xFFFFFFFFu, acc1, 2);
        acc0 += __shfl_xor_sync(0xFFFFFFFFu, acc0, 1);
        acc1 += __shfl_xor_sync(0xFFFFFFFFu, acc1, 1);

        if (lane == 0) {
            float r0 = fast_sigmoid(acc0);
            float r1 = fast_sigmoid(acc1);
            if (EVEN_E) {
                reinterpret_cast<float2*>(out)[g] = make_float2(r0, r1);
            } else {
                out[e0] = r0;
                if (e0 + 1 < E) out[e0 + 1] = r1;
            }
        }

        if (!more) break;
        ss = ssn;
        dd = ddn;
        g  = gn;
    }
}

extern "C" void kernel_launch(void* const* d_in, const int* in_sizes, int n_in,
                              void* d_out, int out_size)
{
    const float* h   = (const float*)d_in[0];
    const int*   src = (const int*)d_in[1];
    const int*   dst = (const int*)d_in[2];
    float*       out = (float*)d_out;

    int E = in_sizes[1];  // number of edges

    int ngroups = (E + 1) / 2;

    const int threads = 256;
    // Fill the chip: 148 SMs x 8 blocks of 256 threads (32-reg budget).
    int max_blocks = 148 * 8;
    long long need_blocks = ((long long)ngroups * 8 + threads - 1) / threads;
    int blocks = (int)(need_blocks < max_blocks ? need_blocks : max_blocks);
    if (blocks < 1) blocks = 1;

    int gstride = blocks * (threads / 8);

    if ((E & 1) == 0) {
        dotpred_kernel<true><<<blocks, threads>>>(h, src, dst, out, E,
                                                  ngroups, gstride);
    } else {
        dotpred_kernel<false><<<blocks, threads>>>(h, src, dst, out, E,
                                                   ngroups, gstride);
    }
}

// round 11
// speedup vs baseline: 1.1417x; 1.1417x over previous
#include <cuda_runtime.h>
#include <cuda_bf16.h>

// DotPredictor: out[e] = sigmoid(dot(h[src[e]], h[dst[e]])), D = 64 fp32.
// Indices are int32 (JAX x64 disabled).
// Fast path (E % 4 == 0): 8 lanes per group, 4 edges (2 pairs) per group.
// Pair 2's rows are prefetched into L1 (reg-free) before pair 1 is processed,
// so pair 2's LDGs hit L1 instead of paying L2 latency. One STG.128 stores
// all 4 results. Fallback kernel = proven R5/R9 2-edge structure.

#define D 64

__device__ __forceinline__ float fast_sigmoid(float x)
{
    float t;
    asm("tanh.approx.f32 %0, %1;" : "=f"(t) : "f"(x * 0.5f));
    return fmaf(t, 0.5f, 0.5f);
}

__device__ __forceinline__ void prefetch_l1(const void* p)
{
    asm volatile("prefetch.global.L1 [%0];" :: "l"(p));
}

// Processes one edge pair: returns the two reduced dot products on lane 0.
__device__ __forceinline__ void edge_pair(
    const float* __restrict__ h, int s0i, int d0i, int s1i, int d1i,
    int lane, float& r0, float& r1)
{
    const float4* __restrict__ s0p =
        reinterpret_cast<const float4*>(h + (long long)s0i * D);
    const float4* __restrict__ d0p =
        reinterpret_cast<const float4*>(h + (long long)d0i * D);
    const float4* __restrict__ s1p =
        reinterpret_cast<const float4*>(h + (long long)s1i * D);
    const float4* __restrict__ d1p =
        reinterpret_cast<const float4*>(h + (long long)d1i * D);

    float4 a0 = s0p[lane];
    float4 a1 = s0p[lane + 8];
    float4 b0 = d0p[lane];
    float4 b1 = d0p[lane + 8];
    float4 c0 = s1p[lane];
    float4 c1 = s1p[lane + 8];
    float4 f0 = d1p[lane];
    float4 f1 = d1p[lane + 8];

    float acc0 = a0.x * b0.x;
    float acc1 = c0.x * f0.x;
    acc0 = fmaf(a0.y, b0.y, acc0);
    acc1 = fmaf(c0.y, f0.y, acc1);
    acc0 = fmaf(a0.z, b0.z, acc0);
    acc1 = fmaf(c0.z, f0.z, acc1);
    acc0 = fmaf(a0.w, b0.w, acc0);
    acc1 = fmaf(c0.w, f0.w, acc1);
    acc0 = fmaf(a1.x, b1.x, acc0);
    acc1 = fmaf(c1.x, f1.x, acc1);
    acc0 = fmaf(a1.y, b1.y, acc0);
    acc1 = fmaf(c1.y, f1.y, acc1);
    acc0 = fmaf(a1.z, b1.z, acc0);
    acc1 = fmaf(c1.z, f1.z, acc1);
    acc0 = fmaf(a1.w, b1.w, acc0);
    acc1 = fmaf(c1.w, f1.w, acc1);

    acc0 += __shfl_xor_sync(0xFFFFFFFFu, acc0, 4);
    acc1 += __shfl_xor_sync(0xFFFFFFFFu, acc1, 4);
    acc0 += __shfl_xor_sync(0xFFFFFFFFu, acc0, 2);
    acc1 += __shfl_xor_sync(0xFFFFFFFFu, acc1, 2);
    acc0 += __shfl_xor_sync(0xFFFFFFFFu, acc0, 1);
    acc1 += __shfl_xor_sync(0xFFFFFFFFu, acc1, 1);

    r0 = acc0;
    r1 = acc1;
}

// Fast path: E % 4 == 0. 4 edges per 8-lane group, L1 prefetch for pair 2.
__global__ void __launch_bounds__(256) dotpred_kernel4(
    const float* __restrict__ h,
    const int* __restrict__ src,
    const int* __restrict__ dst,
    float* __restrict__ out,
    int ngroups)
{
    int gid   = blockIdx.x * blockDim.x + threadIdx.x;
    int group = gid >> 3;            // 8 lanes per group
    int lane  = gid & 7;
    if (group >= ngroups) return;

    // 4 edges' indices in one int4 each (16B aligned)
    int4 ss = reinterpret_cast<const int4*>(src)[group];
    int4 dd = reinterpret_cast<const int4*>(dst)[group];

    // Prefetch pair 2's four rows into L1 (reg-free, fire-and-forget).
    // lane*32: 8 lanes cover 256 B = both 128B lines of each row.
    {
        const char* hs2 = reinterpret_cast<const char*>(h + (long long)ss.z * D);
        const char* hd2 = reinterpret_cast<const char*>(h + (long long)dd.z * D);
        const char* hs3 = reinterpret_cast<const char*>(h + (long long)ss.w * D);
        const char* hd3 = reinterpret_cast<const char*>(h + (long long)dd.w * D);
        int off = lane * 32;
        prefetch_l1(hs2 + off);
        prefetch_l1(hd2 + off);
        prefetch_l1(hs3 + off);
        prefetch_l1(hd3 + off);
    }

    // Pair 1 (pays L2 latency; prefetches migrate pair 2 meanwhile)
    float r0, r1;
    edge_pair(h, ss.x, dd.x, ss.y, dd.y, lane, r0, r1);

    // Pair 2 (L1 hits)
    float r2, r3;
    edge_pair(h, ss.z, dd.z, ss.w, dd.w, lane, r2, r3);

    if (lane == 0) {
        float4 res;
        res.x = fast_sigmoid(r0);
        res.y = fast_sigmoid(r1);
        res.z = fast_sigmoid(r2);
        res.w = fast_sigmoid(r3);
        reinterpret_cast<float4*>(out)[group] = res;
    }
}

// Fallback: any E. 2 edges per 8-lane group with tail guards (R9 structure).
__global__ void __launch_bounds__(256) dotpred_kernel2(
    const float* __restrict__ h,
    const int* __restrict__ src,
    const int* __restrict__ dst,
    float* __restrict__ out,
    int E)
{
    int gid   = blockIdx.x * blockDim.x + threadIdx.x;
    int group = gid >> 3;
    int lane  = gid & 7;
    int e0 = group * 2;
    if (e0 >= E) return;
    bool has_e1 = (e0 + 1 < E);

    int2 ss = reinterpret_cast<const int2*>(src)[group];
    int2 dd = reinterpret_cast<const int2*>(dst)[group];
    int s1i = has_e1 ? ss.y : ss.x;
    int d1i = has_e1 ? dd.y : dd.x;

    float r0, r1;
    edge_pair(h, ss.x, dd.x, s1i, d1i, lane, r0, r1);

    if (lane == 0) {
        out[e0] = fast_sigmoid(r0);
        if (has_e1) out[e0 + 1] = fast_sigmoid(r1);
    }
}

extern "C" void kernel_launch(void* const* d_in, const int* in_sizes, int n_in,
                              void* d_out, int out_size)
{
    const float* h   = (const float*)d_in[0];
    const int*   src = (const int*)d_in[1];
    const int*   dst = (const int*)d_in[2];
    float*       out = (float*)d_out;

    int E = in_sizes[1];  // number of edges
    const int threads = 256;

    if ((E & 3) == 0) {
        int ngroups = E / 4;
        long long total_threads = (long long)ngroups * 8;
        int blocks = (int)((total_threads + threads - 1) / threads);
        dotpred_kernel4<<<blocks, threads>>>(h, src, dst, out, ngroups);
    } else {
        long long groups = ((long long)E + 1) / 2;
        long long total_threads = groups * 8;
        int blocks = (int)((total_threads + threads - 1) / threads);
        dotpred_kernel2<<<blocks, threads>>>(h, src, dst, out, E);
    }
}

// round 12
// speedup vs baseline: 1.2452x; 1.0907x over previous
#include <cuda_runtime.h>
#include <cuda_bf16.h>

// DotPredictor: out[e] = sigmoid(dot(h[src[e]], h[dst[e]])), D = 64 fp32.
// Indices are int32 (JAX x64 disabled).
// 8 lanes per group, 2 edges per group; 8 LDG.128/thread, each warp-level
// LDG covers full 128B lines (wavefront-optimal). Plain 6-shuffle reduction
// (results valid on all lanes) -> lane 0 stores edge0, lane 1 stores edge1.
// 32-bit address math (N*D = 3.2M floats fits int). tanh.approx sigmoid.
// Proven-optimal R5 register/occupancy shape (32 regs, ~86% occ).

#define D 64

__device__ __forceinline__ float fast_sigmoid(float x)
{
    // sigmoid(x) = 0.5*tanh(x/2) + 0.5 ; tanh.approx err ~2^-11 << 1e-3 budget
    float t;
    asm("tanh.approx.f32 %0, %1;" : "=f"(t) : "f"(x * 0.5f));
    return fmaf(t, 0.5f, 0.5f);
}

template <bool EVEN_E>
__global__ void __launch_bounds__(256) dotpred_kernel(
    const float* __restrict__ h,
    const int* __restrict__ src,
    const int* __restrict__ dst,
    float* __restrict__ out,
    int E)
{
    int gid   = blockIdx.x * blockDim.x + threadIdx.x;
    int group = gid >> 3;            // 8 lanes per group
    int lane  = gid & 7;
    int e0 = group * 2;
    if (e0 >= E) return;

    // Vectorized index loads: edge pair is 8B-aligned in src/dst
    int2 ss = reinterpret_cast<const int2*>(src)[group];
    int2 dd = reinterpret_cast<const int2*>(dst)[group];

    int s1i, d1i;
    if (EVEN_E) {
        s1i = ss.y;
        d1i = dd.y;
    } else {
        bool has_e1 = (e0 + 1 < E);
        s1i = has_e1 ? ss.y : ss.x;
        d1i = has_e1 ? dd.y : dd.x;
    }

    // 32-bit offsets: max index*D = 50000*64 = 3.2M, fits int
    const float4* __restrict__ s0p = reinterpret_cast<const float4*>(h + (ss.x << 6));
    const float4* __restrict__ d0p = reinterpret_cast<const float4*>(h + (dd.x << 6));
    const float4* __restrict__ s1p = reinterpret_cast<const float4*>(h + (s1i << 6));
    const float4* __restrict__ d1p = reinterpret_cast<const float4*>(h + (d1i << 6));

    // 8 independent 16B loads; each warp-level LDG covers 4 full 128B lines
    float4 a0 = s0p[lane];
    float4 a1 = s0p[lane + 8];
    float4 b0 = d0p[lane];
    float4 b1 = d0p[lane + 8];
    float4 c0 = s1p[lane];
    float4 c1 = s1p[lane + 8];
    float4 f0 = d1p[lane];
    float4 f1 = d1p[lane + 8];

    float acc0 = a0.x * b0.x;
    float acc1 = c0.x * f0.x;
    acc0 = fmaf(a0.y, b0.y, acc0);
    acc1 = fmaf(c0.y, f0.y, acc1);
    acc0 = fmaf(a0.z, b0.z, acc0);
    acc1 = fmaf(c0.z, f0.z, acc1);
    acc0 = fmaf(a0.w, b0.w, acc0);
    acc1 = fmaf(c0.w, f0.w, acc1);
    acc0 = fmaf(a1.x, b1.x, acc0);
    acc1 = fmaf(c1.x, f1.x, acc1);
    acc0 = fmaf(a1.y, b1.y, acc0);
    acc1 = fmaf(c1.y, f1.y, acc1);
    acc0 = fmaf(a1.z, b1.z, acc0);
    acc1 = fmaf(c1.z, f1.z, acc1);
    acc0 = fmaf(a1.w, b1.w, acc0);
    acc1 = fmaf(c1.w, f1.w, acc1);

    // Plain reduction; after this both sums are valid on ALL 8 lanes
    acc0 += __shfl_xor_sync(0xFFFFFFFFu, acc0, 4);
    acc1 += __shfl_xor_sync(0xFFFFFFFFu, acc1, 4);
    acc0 += __shfl_xor_sync(0xFFFFFFFFu, acc0, 2);
    acc1 += __shfl_xor_sync(0xFFFFFFFFu, acc1, 2);
    acc0 += __shfl_xor_sync(0xFFFFFFFFu, acc0, 1);
    acc1 += __shfl_xor_sync(0xFFFFFFFFu, acc1, 1);

    // Distributed epilogue: lane 0 -> edge0, lane 1 -> edge1 (coalesced pair)
    if (EVEN_E) {
        if (lane < 2) {
            float v = (lane == 0) ? acc0 : acc1;
            out[e0 + lane] = fast_sigmoid(v);
        }
    } else {
        if (lane == 0) out[e0] = fast_sigmoid(acc0);
        if (lane == 1 && (e0 + 1 < E)) out[e0 + 1] = fast_sigmoid(acc1);
    }
}

extern "C" void kernel_launch(void* const* d_in, const int* in_sizes, int n_in,
                              void* d_out, int out_size)
{
    const float* h   = (const float*)d_in[0];
    const int*   src = (const int*)d_in[1];
    const int*   dst = (const int*)d_in[2];
    float*       out = (float*)d_out;

    int E = in_sizes[1];  // number of edges

    long long groups = ((long long)E + 1) / 2;
    long long total_threads = groups * 8;
    const int threads = 256;
    int blocks = (int)((total_threads + threads - 1) / threads);

    if ((E & 1) == 0) {
        dotpred_kernel<true><<<blocks, threads>>>(h, src, dst, out, E);
    } else {
        dotpred_kernel<false><<<blocks, threads>>>(h, src, dst, out, E);
    }
}